// round 4
// baseline (speedup 1.0000x reference)
#include <cuda_runtime.h>
#include <cuda_bf16.h>

#define ALPHA_MARGIN 1.0f
#define PAIRS 4

__device__ __forceinline__ float pair_partial(float4 a, float4 b) {
    float dx = a.x - b.x, dy = a.y - b.y;
    float dz = a.z - b.z, dw = a.w - b.w;
    return dx * dx + dy * dy + dz * dz + dw * dw;
}

// Merged 4-way warp reduction: folds 4 per-lane partial sums into full warp
// sums using 7 shuffles total. Result routing:
//   lane 0  -> sum(s0), lane 16 -> sum(s1), lane 8 -> sum(s2), lane 24 -> sum(s3)
__device__ __forceinline__ float reduce4(float s0, float s1, float s2, float s3, int lane) {
    // xor-16 merge: u <- pair0 partials in lanes 0-15, pair1 in 16-31
    float u  = (lane & 16) ? s1 : s0;
    float uw = (lane & 16) ? s0 : s1;
    u += __shfl_xor_sync(0xffffffffu, uw, 16);
    float v  = (lane & 16) ? s3 : s2;
    float vw = (lane & 16) ? s2 : s3;
    v += __shfl_xor_sync(0xffffffffu, vw, 16);
    // xor-8 merge: r <- {p0:0-7, p2:8-15, p1:16-23, p3:24-31}
    float r  = (lane & 8) ? v : u;
    float q  = (lane & 8) ? u : v;
    r += __shfl_xor_sync(0xffffffffu, q, 8);
    // finish within 8-lane groups
    r += __shfl_xor_sync(0xffffffffu, r, 4);
    r += __shfl_xor_sync(0xffffffffu, r, 2);
    r += __shfl_xor_sync(0xffffffffu, r, 1);
    return r;
}

// Persistent kernel: 4 pairs per warp-iteration (8 front-batched LDG.128 per
// lane), double-buffered so ~16 loads stay in flight through the reduction.
__global__ __launch_bounds__(256) void contrastive_loss_kernel(
    const float* __restrict__ X,
    const int*   __restrict__ y,
    float*       __restrict__ out,
    int n_pairs)
{
    const int lane   = threadIdx.x & 31;
    const int gwarp  = (blockIdx.x * blockDim.x + threadIdx.x) >> 5;
    const int nwarps = (gridDim.x * blockDim.x) >> 5;
    const int stride = nwarps * PAIRS;

    // epilogue lane mapping: lane0->pair0, lane16->pair1, lane8->pair2, lane24->pair3
    const bool epi_lane = (lane & 7) == 0;
    const int  epi_idx  = ((lane >> 4) & 1) + ((lane >> 2) & 2);

    const float4* Xv = reinterpret_cast<const float4*>(X);

    int p = gwarp * PAIRS;

    float4 a[PAIRS], b[PAIRS];
    int adj = 0;

    #pragma unroll
    for (int i = 0; i < PAIRS; i++) {
        if (p + i < n_pairs) {
            const float4* r = Xv + (size_t)(p + i) * 64;
            a[i] = __ldg(r + lane);
            b[i] = __ldg(r + 32 + lane);
        }
    }
    if (epi_lane && p + epi_idx < n_pairs) adj = __ldg(y + p + epi_idx);

    while (p < n_pairs) {
        const int pn = p + stride;

        // Prefetch next iteration before reducing current
        float4 na[PAIRS], nb[PAIRS];
        int nadj = 0;
        #pragma unroll
        for (int i = 0; i < PAIRS; i++) {
            if (pn + i < n_pairs) {
                const float4* r = Xv + (size_t)(pn + i) * 64;
                na[i] = __ldg(r + lane);
                nb[i] = __ldg(r + 32 + lane);
            }
        }
        if (epi_lane && pn + epi_idx < n_pairs) nadj = __ldg(y + pn + epi_idx);

        float s0 = pair_partial(a[0], b[0]);
        float s1 = pair_partial(a[1], b[1]);
        float s2 = pair_partial(a[2], b[2]);
        float s3 = pair_partial(a[3], b[3]);

        float s = reduce4(s0, s1, s2, s3, lane);

        if (epi_lane && p + epi_idx < n_pairs) {
            float loss = (adj == 1) ? s
                       : (adj == 0) ? fmaxf(ALPHA_MARGIN - s, 0.0f)
                       : 0.0f;
            out[p + epi_idx] = loss;
        }

        #pragma unroll
        for (int i = 0; i < PAIRS; i++) { a[i] = na[i]; b[i] = nb[i]; }
        adj = nadj;
        p = pn;
    }
}

extern "C" void kernel_launch(void* const* d_in, const int* in_sizes, int n_in,
                              void* d_out, int out_size)
{
    const float* X = (const float*)d_in[0];
    const int*   y = (const int*)d_in[1];
    float*       out = (float*)d_out;

    int n_pairs = out_size;      // B*N*N = 524288
    int blocks  = 2048;
    contrastive_loss_kernel<<<blocks, 256>>>(X, y, out, n_pairs);
}

// round 5
// speedup vs baseline: 1.0004x; 1.0004x over previous
#include <cuda_runtime.h>
#include <cuda_bf16.h>

#define ALPHA_MARGIN 1.0f

// Fully-resident persistent kernel: grid sized so every CTA is resident from
// wave 1 (5 CTAs/SM x 148 SMs). Each warp: 2 pairs per iteration, 4 coalesced
// LDG.128 per lane, next iteration prefetched before the current reduction.
__global__ __launch_bounds__(256) void contrastive_loss_kernel(
    const float* __restrict__ X,
    const int*   __restrict__ y,
    float*       __restrict__ out,
    int n_pairs)
{
    const int lane   = threadIdx.x & 31;
    const int gwarp  = (blockIdx.x * blockDim.x + threadIdx.x) >> 5;
    const int nwarps = (gridDim.x * blockDim.x) >> 5;
    const int stride = nwarps * 2;

    const float4* Xv = reinterpret_cast<const float4*>(X);
    int p = gwarp * 2;

    float4 a0, b0, a1, b1;
    if (p < n_pairs) {
        const float4* r0 = Xv + (size_t)p * 64;
        a0 = __ldg(r0 + lane);
        b0 = __ldg(r0 + 32 + lane);
    }
    if (p + 1 < n_pairs) {
        const float4* r1 = Xv + (size_t)(p + 1) * 64;
        a1 = __ldg(r1 + lane);
        b1 = __ldg(r1 + 32 + lane);
    }

    while (p < n_pairs) {
        const int pn = p + stride;

        // Prefetch next iteration before reducing current
        float4 na0, nb0, na1, nb1;
        if (pn < n_pairs) {
            const float4* r0 = Xv + (size_t)pn * 64;
            na0 = __ldg(r0 + lane);
            nb0 = __ldg(r0 + 32 + lane);
        }
        if (pn + 1 < n_pairs) {
            const float4* r1 = Xv + (size_t)(pn + 1) * 64;
            na1 = __ldg(r1 + lane);
            nb1 = __ldg(r1 + 32 + lane);
        }

        // Pair p
        {
            float dx = a0.x - b0.x, dy = a0.y - b0.y;
            float dz = a0.z - b0.z, dw = a0.w - b0.w;
            float s = dx * dx + dy * dy + dz * dz + dw * dw;
            #pragma unroll
            for (int o = 16; o > 0; o >>= 1)
                s += __shfl_xor_sync(0xffffffffu, s, o);
            if (lane == 0) {
                int adj = y[p];
                out[p] = (adj == 1) ? s
                       : (adj == 0) ? fmaxf(ALPHA_MARGIN - s, 0.0f)
                       : 0.0f;
            }
        }

        // Pair p+1
        if (p + 1 < n_pairs) {
            float dx = a1.x - b1.x, dy = a1.y - b1.y;
            float dz = a1.z - b1.z, dw = a1.w - b1.w;
            float s = dx * dx + dy * dy + dz * dz + dw * dw;
            #pragma unroll
            for (int o = 16; o > 0; o >>= 1)
                s += __shfl_xor_sync(0xffffffffu, s, o);
            if (lane == 0) {
                int adj = y[p + 1];
                out[p + 1] = (adj == 1) ? s
                           : (adj == 0) ? fmaxf(ALPHA_MARGIN - s, 0.0f)
                           : 0.0f;
            }
        }

        a0 = na0; b0 = nb0; a1 = na1; b1 = nb1;
        p = pn;
    }
}

extern "C" void kernel_launch(void* const* d_in, const int* in_sizes, int n_in,
                              void* d_out, int out_size)
{
    const float* X = (const float*)d_in[0];
    const int*   y = (const int*)d_in[1];
    float*       out = (float*)d_out;

    int n_pairs = out_size;                 // B*N*N = 524288
    int blocks  = 5 * 148;                  // fully resident: 5 CTAs/SM (46 regs/thr)
    contrastive_loss_kernel<<<blocks, 256>>>(X, y, out, n_pairs);
}